// round 14
// baseline (speedup 1.0000x reference)
#include <cuda_runtime.h>
#include <cuda_fp16.h>
#include <math.h>
#include <stdint.h>

#define T_TOK 2048
#define SEQ   1024
#define BATCH 2
#define HID   768
#define NHEAD 12
#define HDIM  64
#define NLAYER 12
#define FFI   3072
#define VOCAB 50257

// ---------------- scratch (device globals: allocation-free) ----------------
__device__ float  g_x[T_TOK * HID];
__device__ __half g_h[T_TOK * HID];
__device__ __half g_q[T_TOK * HID];
__device__ __half g_k[T_TOK * HID];
__device__ __half g_v[T_TOK * HID];
__device__ __half g_a[T_TOK * HID];
__device__ __half g_ff[T_TOK * FFI];
// fp16 weight copies
__device__ __half g_wq[NLAYER * HID * HID];
__device__ __half g_wk[NLAYER * HID * HID];
__device__ __half g_wv[NLAYER * HID * HID];
__device__ __half g_wo[NLAYER * HID * HID];
__device__ __half g_w1[NLAYER * FFI * HID];
__device__ __half g_w2[NLAYER * HID * FFI];
__device__ __half g_wlm[VOCAB * HID];

// ---------------- helpers ----------------
__device__ __forceinline__ float gelu1(float x) {
    return 0.5f * x * (1.0f + erff(x * 0.70710678118654752f));
}
__device__ __forceinline__ void mma_f16(float d[4], const uint32_t a[4], const uint32_t b[2]) {
    asm volatile(
        "mma.sync.aligned.m16n8k16.row.col.f32.f16.f16.f32 "
        "{%0,%1,%2,%3}, {%4,%5,%6,%7}, {%8,%9}, {%0,%1,%2,%3};\n"
        : "+f"(d[0]), "+f"(d[1]), "+f"(d[2]), "+f"(d[3])
        : "r"(a[0]), "r"(a[1]), "r"(a[2]), "r"(a[3]), "r"(b[0]), "r"(b[1]));
}
__device__ __forceinline__ void ldsm_x4(uint32_t* r, uint32_t addr) {
    asm volatile("ldmatrix.sync.aligned.m8n8.x4.shared.b16 {%0,%1,%2,%3}, [%4];"
        : "=r"(r[0]), "=r"(r[1]), "=r"(r[2]), "=r"(r[3]) : "r"(addr));
}
__device__ __forceinline__ void ldsm_x4_t(uint32_t* r, uint32_t addr) {
    asm volatile("ldmatrix.sync.aligned.m8n8.x4.trans.shared.b16 {%0,%1,%2,%3}, [%4];"
        : "=r"(r[0]), "=r"(r[1]), "=r"(r[2]), "=r"(r[3]) : "r"(addr));
}
__device__ __forceinline__ void cp_async16(uint32_t dst, const void* src, int sz) {
    asm volatile("cp.async.cg.shared.global [%0], [%1], 16, %2;\n"
                 :: "r"(dst), "l"(src), "r"(sz));
}
#define CP_COMMIT() asm volatile("cp.async.commit_group;\n" ::: "memory")
#define CP_WAIT2()  asm volatile("cp.async.wait_group 2;\n" ::: "memory")
#define CP_WAIT1()  asm volatile("cp.async.wait_group 1;\n" ::: "memory")

// ---------------- embeddings ----------------
__global__ void embed_kernel(const int* __restrict__ ids,
                             const float* __restrict__ tok,
                             const float* __restrict__ pos,
                             float* __restrict__ x) {
    int idx = blockIdx.x * blockDim.x + threadIdx.x;
    if (idx >= T_TOK * HID) return;
    int t = idx / HID;
    int hh = idx - t * HID;
    int s = t % SEQ;
    int id = ids[t];
    x[idx] = tok[(size_t)id * HID + hh] + pos[(size_t)s * HID + hh];
}

// ---------------- fp16 weight copy (8 floats -> uint4 store) --------------
__global__ void cvt_half_k(const float* __restrict__ in, __half* __restrict__ outp, int n8) {
    const int i0 = blockIdx.x * 1024 + threadIdx.x;
    #pragma unroll
    for (int c = 0; c < 4; c++) {
        const int i = i0 + c * 256;
        if (i < n8) {
            float4 a = reinterpret_cast<const float4*>(in)[2 * i];
            float4 b = reinterpret_cast<const float4*>(in)[2 * i + 1];
            __half2 h0 = __floats2half2_rn(a.x, a.y);
            __half2 h1 = __floats2half2_rn(a.z, a.w);
            __half2 h2 = __floats2half2_rn(b.x, b.y);
            __half2 h3 = __floats2half2_rn(b.z, b.w);
            uint4 u;
            u.x = *reinterpret_cast<uint32_t*>(&h0);
            u.y = *reinterpret_cast<uint32_t*>(&h1);
            u.z = *reinterpret_cast<uint32_t*>(&h2);
            u.w = *reinterpret_cast<uint32_t*>(&h3);
            reinterpret_cast<uint4*>(outp)[i] = u;
        }
    }
}

// ---------------- layernorm: one warp per row, register-resident ----------
__global__ __launch_bounds__(256) void layernorm_kernel(
    const float* __restrict__ x, const float* __restrict__ w,
    const float* __restrict__ b, __half* __restrict__ out)
{
    const int warp = threadIdx.x >> 5;
    const int lane = threadIdx.x & 31;
    const int row  = blockIdx.x * 8 + warp;
    const float* xr = x + (size_t)row * HID;
    __half* orow = out + (size_t)row * HID;

    float4 vv[6];
    #pragma unroll
    for (int i = 0; i < 6; i++)
        vv[i] = *reinterpret_cast<const float4*>(&xr[(i * 32 + lane) * 4]);

    float s = 0.f;
    #pragma unroll
    for (int i = 0; i < 6; i++) s += vv[i].x + vv[i].y + vv[i].z + vv[i].w;
    #pragma unroll
    for (int o = 16; o > 0; o >>= 1) s += __shfl_xor_sync(0xffffffffu, s, o);
    const float mean = s * (1.0f / (float)HID);

    float vs = 0.f;
    #pragma unroll
    for (int i = 0; i < 6; i++) {
        float d0 = vv[i].x - mean, d1 = vv[i].y - mean;
        float d2 = vv[i].z - mean, d3 = vv[i].w - mean;
        vs += d0 * d0 + d1 * d1 + d2 * d2 + d3 * d3;
    }
    #pragma unroll
    for (int o = 16; o > 0; o >>= 1) vs += __shfl_xor_sync(0xffffffffu, vs, o);
    const float inv = rsqrtf(vs * (1.0f / (float)HID) + 1e-5f);

    #pragma unroll
    for (int i = 0; i < 6; i++) {
        const int c = (i * 32 + lane) * 4;
        float4 wv = *reinterpret_cast<const float4*>(&w[c]);
        float4 bv = *reinterpret_cast<const float4*>(&b[c]);
        float y0 = (vv[i].x - mean) * inv * wv.x + bv.x;
        float y1 = (vv[i].y - mean) * inv * wv.y + bv.y;
        float y2 = (vv[i].z - mean) * inv * wv.z + bv.z;
        float y3 = (vv[i].w - mean) * inv * wv.w + bv.w;
        __half2 h0 = __floats2half2_rn(y0, y1);
        __half2 h1 = __floats2half2_rn(y2, y3);
        uint2 u;
        u.x = *reinterpret_cast<uint32_t*>(&h0);
        u.y = *reinterpret_cast<uint32_t*>(&h1);
        *reinterpret_cast<uint2*>(&orow[c]) = u;
    }
}

// ---------------- FP16 mma GEMM, 4-stage cp.async, ldmatrix ---------------
#define GSTAGES 4
#define HSTR 40

template<int BM, int BN, bool GELU, bool OUTHALF>
__device__ __forceinline__ void gemm_f16_dev(
    const __half* __restrict__ A, const __half* __restrict__ W,
    const float* __restrict__ bias, const float* __restrict__ res,
    void* __restrict__ Cv, int M, int N, int K)
{
    extern __shared__ __half smh[];
    constexpr int SH = (BM + BN) * HSTR;
    constexpr int MT = BM / 32;
    constexpr int NT = BN / 32;
    constexpr int WMROWS = BM / 2;
    constexpr int WNCOLS = BN / 4;

    const int tid  = threadIdx.x;
    const int warp = tid >> 5;
    const int lane = tid & 31;
    const int g    = lane >> 2;
    const int tig  = lane & 3;
    const int wm   = warp & 1;
    const int wn   = warp >> 1;

    const int m0 = blockIdx.y * BM;
    const int n0 = blockIdx.x * BN;

    const __half* gB;
    uint32_t dB;
    int bsz;
    if constexpr (BN == 128) {
        const int brl = tid >> 1;
        const int bk  = (tid & 1) << 4;
        const int bn  = n0 + brl;
        bsz = (bn < N) ? 16 : 0;
        gB = W + (size_t)(bn < N ? bn : 0) * K + bk;
        dB = (uint32_t)__cvta_generic_to_shared(smh + BM * HSTR + brl * HSTR + bk);
    } else {
        const int brl = tid >> 2;
        const int bk  = (tid & 3) << 3;
        const int bn  = n0 + brl;
        bsz = (bn < N) ? 16 : 0;
        gB = W + (size_t)(bn < N ? bn : 0) * K + bk;
        dB = (uint32_t)__cvta_generic_to_shared(smh + BM * HSTR + brl * HSTR + bk);
    }

    const __half* gA;
    uint32_t dA;
    if constexpr (BM == 128) {
        const int arl = tid >> 1;
        const int ak  = (tid & 1) << 4;
        gA = A + (size_t)(m0 + arl) * K + ak;
        dA = (uint32_t)__cvta_generic_to_shared(smh + arl * HSTR + ak);
    } else {
        const int arl = tid >> 2;
        const int ak  = (tid & 3) << 3;
        gA = A + (size_t)(m0 + arl) * K + ak;
        dA = (uint32_t)__cvta_generic_to_shared(smh + arl * HSTR + ak);
    }
    const uint32_t stageB = SH * 2u;

    const int alr = lane & 15;
    const int alc = (lane >> 4) * 8;
    const int bnr = (lane & 7) + ((lane >> 4) & 1) * 8;
    const int bkc = ((lane >> 3) & 1) * 8;

    float acc[MT][NT][4];
    #pragma unroll
    for (int i = 0; i < MT; i++)
        #pragma unroll
        for (int j = 0; j < NT; j++)
            #pragma unroll
            for (int r = 0; r < 4; r++) acc[i][j][r] = 0.f;

    const int NIT = K >> 5;

    #define FILLG2(it_) do { \
        const uint32_t _o = ((it_) & 3) * stageB; \
        const int _kb = (it_) << 5; \
        cp_async16(dA + _o, gA + _kb, 16); \
        if constexpr (BM == 128) cp_async16(dA + _o + 16, gA + _kb + 8, 16); \
        cp_async16(dB + _o, gB + _kb, bsz); \
        if constexpr (BN == 128) cp_async16(dB + _o + 16, gB + _kb + 8, bsz); \
    } while (0)

    #pragma unroll
    for (int s = 0; s < GSTAGES - 1; s++) {
        if (s < NIT) FILLG2(s);
        CP_COMMIT();
    }
    CP_WAIT2();
    __syncthreads();

    for (int it = 0; it < NIT; it++) {
        const int buf = it & 3;
        const __half* bufA = smh + buf * SH;
        const __half* bufB = bufA + BM * HSTR;

        #pragma unroll
        for (int s = 0; s < 2; s++) {
            uint32_t af[MT][4];
            #pragma unroll
            for (int mt = 0; mt < MT; mt++)
                ldsm_x4(af[mt], (uint32_t)__cvta_generic_to_shared(
                    &bufA[(wm * WMROWS + mt * 16 + alr) * HSTR + s * 16 + alc]));
            uint32_t bf[NT][2];
            #pragma unroll
            for (int p = 0; p < NT / 2; p++) {
                uint32_t bq[4];
                ldsm_x4(bq, (uint32_t)__cvta_generic_to_shared(
                    &bufB[(wn * WNCOLS + p * 16 + bnr) * HSTR + s * 16 + bkc]));
                bf[2 * p][0] = bq[0]; bf[2 * p][1] = bq[1];
                bf[2 * p + 1][0] = bq[2]; bf[2 * p + 1][1] = bq[3];
            }
            #pragma unroll
            for (int mt = 0; mt < MT; mt++)
                #pragma unroll
                for (int nt = 0; nt < NT; nt++)
                    mma_f16(acc[mt][nt], af[mt], bf[nt]);
        }

        const int nit = it + GSTAGES - 1;
        if (nit < NIT) FILLG2(nit);
        CP_COMMIT();
        CP_WAIT2();
        __syncthreads();
    }
    #undef FILLG2

    float* Cf = (float*)Cv;
    __half* Ch = (__half*)Cv;
    const bool n_even = ((N & 1) == 0);
    #pragma unroll
    for (int mt = 0; mt < MT; mt++) {
        const int r0 = m0 + wm * WMROWS + mt * 16 + g;
        #pragma unroll
        for (int nt = 0; nt < NT; nt++) {
            const int c = n0 + wn * WNCOLS + nt * 8 + tig * 2;
            #pragma unroll
            for (int half_ = 0; half_ < 2; half_++) {
                const int m = r0 + half_ * 8;
                float v0 = acc[mt][nt][half_ * 2 + 0];
                float v1 = acc[mt][nt][half_ * 2 + 1];
                if (n_even && (c + 1) < N) {
                    if (bias) { float2 bv = *reinterpret_cast<const float2*>(&bias[c]); v0 += bv.x; v1 += bv.y; }
                    if (res)  { float2 rv = *reinterpret_cast<const float2*>(&res[(size_t)m * N + c]); v0 += rv.x; v1 += rv.y; }
                    if (GELU) { v0 = gelu1(v0); v1 = gelu1(v1); }
                    if (OUTHALF) {
                        *reinterpret_cast<__half2*>(&Ch[(size_t)m * N + c]) = __floats2half2_rn(v0, v1);
                    } else {
                        *reinterpret_cast<float2*>(&Cf[(size_t)m * N + c]) = make_float2(v0, v1);
                    }
                } else {
                    #pragma unroll
                    for (int q2 = 0; q2 < 2; q2++) {
                        const int n = c + q2;
                        if (n < N) {
                            float val = (q2 == 0) ? v0 : v1;
                            if (bias) val += bias[n];
                            if (res)  val += res[(size_t)m * N + n];
                            if (GELU) val = gelu1(val);
                            if (OUTHALF) Ch[(size_t)m * N + n] = __float2half_rn(val);
                            else         Cf[(size_t)m * N + n] = val;
                        }
                    }
                }
            }
        }
    }
}

template<int BM, int BN, bool GELU, bool OUTHALF>
__global__ __launch_bounds__(256, 2) void gemm_f16_k(
    const __half* __restrict__ A, const __half* __restrict__ W,
    const float* __restrict__ bias, const float* __restrict__ res,
    void* __restrict__ C, int M, int N, int K)
{
    gemm_f16_dev<BM, BN, GELU, OUTHALF>(A, W, bias, res, C, M, N, K);
}

__global__ __launch_bounds__(256, 2) void gemm_f16_qkv_k(
    const __half* __restrict__ A,
    const __half* __restrict__ w0, const __half* __restrict__ w1, const __half* __restrict__ w2,
    __half* __restrict__ o0, __half* __restrict__ o1, __half* __restrict__ o2,
    int M, int N, int K)
{
    const __half* W = (blockIdx.z == 0) ? w0 : ((blockIdx.z == 1) ? w1 : w2);
    __half* C = (blockIdx.z == 0) ? o0 : ((blockIdx.z == 1) ? o1 : o2);
    gemm_f16_dev<128, 128, false, true>(A, W, nullptr, nullptr, (void*)C, M, N, K);
}

#define GEMM_SMEM_128   (GSTAGES * (128 + 128) * HSTR * 2)
#define GEMM_SMEM_64    (GSTAGES * (64 + 64) * HSTR * 2)
#define GEMM_SMEM_64128 (GSTAGES * (64 + 128) * HSTR * 2)

// ---------------- tensor-core flash attention, double-buffered K/V --------
#define ASTR 72

__global__ __launch_bounds__(128) void flash_attn_f16_kernel(
    const __half* __restrict__ q, const __half* __restrict__ k,
    const __half* __restrict__ v, const int* __restrict__ amask,
    __half* __restrict__ out)
{
    __shared__ __half Qs[64 * ASTR];
    __shared__ __half Ks[2][64 * ASTR];
    __shared__ __half Vs[2][64 * ASTR];
    __shared__ int msk[2][64];

    const int qt = gridDim.x - 1 - blockIdx.x;
    const int hh = blockIdx.y;
    const int b  = blockIdx.z;
    const int q0 = qt * 64;
    const int tid = threadIdx.x;
    const int lane = tid & 31;
    const int w = tid >> 5;
    const int tig = lane & 3;
    const int gid = lane >> 2;

    // load + scale Q tile
    {
        const __half2 s125 = __float2half2_rn(0.125f);
        #pragma unroll
        for (int ch = tid; ch < 512; ch += 128) {
            const int row = ch >> 3, part = ch & 7;
            uint4 u = *reinterpret_cast<const uint4*>(
                q + (size_t)(b * SEQ + q0 + row) * HID + hh * HDIM + part * 8);
            __half2* hp = reinterpret_cast<__half2*>(&u);
            hp[0] = __hmul2(hp[0], s125); hp[1] = __hmul2(hp[1], s125);
            hp[2] = __hmul2(hp[2], s125); hp[3] = __hmul2(hp[3], s125);
            *reinterpret_cast<uint4*>(&Qs[row * ASTR + part * 8]) = u;
        }
    }

    // prefetch helper: K/V tile kt_ into buffer bf_
    #define AT_PREFETCH(kt_, bf_) do { \
        _Pragma("unroll") \
        for (int ch = tid; ch < 512; ch += 128) { \
            const int row = ch >> 3, part = ch & 7; \
            const size_t go = (size_t)(b * SEQ + (kt_) * 64 + row) * HID + hh * HDIM + part * 8; \
            cp_async16((uint32_t)__cvta_generic_to_shared(&Ks[bf_][row * ASTR + part * 8]), k + go, 16); \
            cp_async16((uint32_t)__cvta_generic_to_shared(&Vs[bf_][row * ASTR + part * 8]), v + go, 16); \
        } \
        if (tid < 64) msk[bf_][tid] = amask[b * SEQ + (kt_) * 64 + tid]; \
    } while (0)

    AT_PREFETCH(0, 0);
    CP_COMMIT();
    __syncthreads();   // Q visible to all warps

    // Q fragments (registers, whole kernel)
    uint32_t qf[4][4];
    {
        const int r = 16 * w + (lane & 15);
        const int c = (lane >> 4) * 8;
        #pragma unroll
        for (int kk = 0; kk < 4; kk++)
            ldsm_x4(qf[kk], (uint32_t)__cvta_generic_to_shared(&Qs[r * ASTR + kk * 16 + c]));
    }

    float o[8][4];
    #pragma unroll
    for (int i = 0; i < 8; i++)
        #pragma unroll
        for (int j = 0; j < 4; j++) o[i][j] = 0.f;
    float mi0 = -1e30f, mi1 = -1e30f, li0 = 0.f, li1 = 0.f;
    const int row0 = q0 + 16 * w + gid;
    const int row1 = row0 + 8;

    for (int kt = 0; kt <= qt; kt++) {
        const int buf = kt & 1;
        if (kt < qt) AT_PREFETCH(kt + 1, buf ^ 1);
        CP_COMMIT();
        CP_WAIT1();        // tile kt complete (only kt+1 may remain pending)
        __syncthreads();   // all threads' copies visible

        const __half* Kb = Ks[buf];
        const __half* Vb = Vs[buf];
        const int* mk = msk[buf];

        // ---- S = Q K^T ----
        float s[8][4];
        #pragma unroll
        for (int j = 0; j < 8; j++) {
            s[j][0] = s[j][1] = s[j][2] = s[j][3] = 0.f;
            uint32_t kb[8];
            const uint32_t base = (uint32_t)__cvta_generic_to_shared(
                &Kb[(8 * j + (lane & 7)) * ASTR + (lane >> 3) * 8]);
            ldsm_x4(kb, base);
            ldsm_x4(kb + 4, base + 64);
            mma_f16(s[j], qf[0], kb);
            mma_f16(s[j], qf[1], kb + 2);
            mma_f16(s[j], qf[2], kb + 4);
            mma_f16(s[j], qf[3], kb + 6);
        }

        // ---- mask ----
        const bool diag = (kt == qt);
        #pragma unroll
        for (int j = 0; j < 8; j++) {
            const int c0i = kt * 64 + 8 * j + 2 * tig;
            if (mk[8 * j + 2 * tig] == 0)     { s[j][0] = -1e9f; s[j][2] = -1e9f; }
            if (mk[8 * j + 2 * tig + 1] == 0) { s[j][1] = -1e9f; s[j][3] = -1e9f; }
            if (diag) {
                if (c0i > row0)     s[j][0] = -1e9f;
                if (c0i + 1 > row0) s[j][1] = -1e9f;
                if (c0i > row1)     s[j][2] = -1e9f;
                if (c0i + 1 > row1) s[j][3] = -1e9f;
            }
        }

        // ---- online softmax ----
        float m0 = -1e30f, m1 = -1e30f;
        #pragma unroll
        for (int j = 0; j < 8; j++) {
            m0 = fmaxf(m0, fmaxf(s[j][0], s[j][1]));
            m1 = fmaxf(m1, fmaxf(s[j][2], s[j][3]));
        }
        m0 = fmaxf(m0, __shfl_xor_sync(0xffffffffu, m0, 1));
        m0 = fmaxf(m0, __shfl_xor_sync(0xffffffffu, m0, 2));
        m1 = fmaxf(m1, __shfl_xor_sync(0xffffffffu, m1, 1));
        m1 = fmaxf(m1, __shfl_xor_sync(0xffffffffu, m1, 2));
        const float mn0 = fmaxf(mi0, m0);
        const float mn1 = fmaxf(mi1, m1);
        const float sc0 = __expf(mi0 - mn0);
        const float sc1 = __expf(mi1 - mn1);

        uint32_t ph[8][2];
        float ls0 = 0.f, ls1 = 0.f;
        #pragma unroll
        for (int j = 0; j < 8; j++) {
            const float p0 = __expf(s[j][0] - mn0);
            const float p1 = __expf(s[j][1] - mn0);
            const float p2 = __expf(s[j][2] - mn1);
            const float p3 = __expf(s[j][3] - mn1);
            ls0 += p0 + p1; ls1 += p2 + p3;
            __half2 h01 = __floats2half2_rn(p0, p1);
            __half2 h23 = __floats2half2_rn(p2, p3);
            ph[j][0] = *reinterpret_cast<uint32_t*>(&h01);
            ph[j][1] = *reinterpret_cast<uint32_t*>(&h23);
        }
        li0 = li0 * sc0 + ls0;
        li1 = li1 * sc1 + ls1;
        mi0 = mn0; mi1 = mn1;
        #pragma unroll
        for (int dn = 0; dn < 8; dn++) {
            o[dn][0] *= sc0; o[dn][1] *= sc0;
            o[dn][2] *= sc1; o[dn][3] *= sc1;
        }

        // ---- O += P V ----
        #pragma unroll
        for (int kj = 0; kj < 4; kj++) {
            const uint32_t a[4] = {ph[2 * kj][0], ph[2 * kj][1],
                                   ph[2 * kj + 1][0], ph[2 * kj + 1][1]};
            #pragma unroll
            for (int dnp = 0; dnp < 4; dnp++) {
                uint32_t vb[4];
                const uint32_t addr = (uint32_t)__cvta_generic_to_shared(
                    &Vb[(16 * kj + (lane & 7) + ((lane >> 3) & 1) * 8) * ASTR
                        + 16 * dnp + (lane >> 4) * 8]);
                ldsm_x4_t(vb, addr);
                mma_f16(o[2 * dnp], a, vb);
                mma_f16(o[2 * dnp + 1], a, vb + 2);
            }
        }
        __syncthreads();   // compute done before next iter's prefetch overwrites buf^1
    }
    #undef AT_PREFETCH

    li0 += __shfl_xor_sync(0xffffffffu, li0, 1);
    li0 += __shfl_xor_sync(0xffffffffu, li0, 2);
    li1 += __shfl_xor_sync(0xffffffffu, li1, 1);
    li1 += __shfl_xor_sync(0xffffffffu, li1, 2);
    const float inv0 = 1.0f / li0;
    const float inv1 = 1.0f / li1;
    #pragma unroll
    for (int dn = 0; dn < 8; dn++) {
        const int cb = hh * HDIM + 8 * dn + 2 * tig;
        __half2 h0 = __floats2half2_rn(o[dn][0] * inv0, o[dn][1] * inv0);
        __half2 h1 = __floats2half2_rn(o[dn][2] * inv1, o[dn][3] * inv1);
        *reinterpret_cast<__half2*>(&out[(size_t)(b * SEQ + row0) * HID + cb]) = h0;
        *reinterpret_cast<__half2*>(&out[(size_t)(b * SEQ + row1) * HID + cb]) = h1;
    }
}

// ---------------- launcher ----------------
extern "C" void kernel_launch(void* const* d_in, const int* in_sizes, int n_in,
                              void* d_out, int out_size) {
    const int*   input_ids = (const int*)d_in[0];
    const int*   attn_mask = (const int*)d_in[1];
    const float* tok_emb   = (const float*)d_in[2];
    const float* pos_emb   = (const float*)d_in[3];
    const float* ln1_w     = (const float*)d_in[4];
    const float* ln1_b     = (const float*)d_in[5];
    const float* qw        = (const float*)d_in[6];
    const float* kw        = (const float*)d_in[7];
    const float* vw        = (const float*)d_in[8];
    const float* ow        = (const float*)d_in[9];
    const float* ob        = (const float*)d_in[10];
    const float* ln2_w     = (const float*)d_in[11];
    const float* ln2_b     = (const float*)d_in[12];
    const float* w1        = (const float*)d_in[13];
    const float* b1        = (const float*)d_in[14];
    const float* w2        = (const float*)d_in[15];
    const float* b2        = (const float*)d_in[16];
    const float* lnf_w     = (const float*)d_in[17];
    const float* lnf_b     = (const float*)d_in[18];
    const float* lm_w      = (const float*)d_in[19];
    float* out = (float*)d_out;

    float *x;
    __half *h, *q, *k, *v, *a, *ff, *wq, *wk, *wv, *wo, *cw1, *cw2, *wlm;
    cudaGetSymbolAddress((void**)&x,  g_x);
    cudaGetSymbolAddress((void**)&h,  g_h);
    cudaGetSymbolAddress((void**)&q,  g_q);
    cudaGetSymbolAddress((void**)&k,  g_k);
    cudaGetSymbolAddress((void**)&v,  g_v);
    cudaGetSymbolAddress((void**)&a,  g_a);
    cudaGetSymbolAddress((void**)&ff, g_ff);
    cudaGetSymbolAddress((void**)&wq, g_wq);
    cudaGetSymbolAddress((void**)&wk, g_wk);
    cudaGetSymbolAddress((void**)&wv, g_wv);
    cudaGetSymbolAddress((void**)&wo, g_wo);
    cudaGetSymbolAddress((void**)&cw1, g_w1);
    cudaGetSymbolAddress((void**)&cw2, g_w2);
    cudaGetSymbolAddress((void**)&wlm, g_wlm);

    cudaFuncSetAttribute((const void*)gemm_f16_k<128, 128, false, false>,
                         cudaFuncAttributeMaxDynamicSharedMemorySize, GEMM_SMEM_128);
    cudaFuncSetAttribute((const void*)gemm_f16_k<64, 128, true, true>,
                         cudaFuncAttributeMaxDynamicSharedMemorySize, GEMM_SMEM_64128);
    cudaFuncSetAttribute((const void*)gemm_f16_k<64, 64, false, false>,
                         cudaFuncAttributeMaxDynamicSharedMemorySize, GEMM_SMEM_64);
    cudaFuncSetAttribute((const void*)gemm_f16_qkv_k,
                         cudaFuncAttributeMaxDynamicSharedMemorySize, GEMM_SMEM_128);

    // one-time-per-launch fp16 weight conversion
    {
        const int nqk = NLAYER * HID * HID / 8;
        cvt_half_k<<<(nqk + 1023) / 1024, 256>>>(qw, wq, nqk);
        cvt_half_k<<<(nqk + 1023) / 1024, 256>>>(kw, wk, nqk);
        cvt_half_k<<<(nqk + 1023) / 1024, 256>>>(vw, wv, nqk);
        cvt_half_k<<<(nqk + 1023) / 1024, 256>>>(ow, wo, nqk);
        const int nff = NLAYER * FFI * HID / 8;
        cvt_half_k<<<(nff + 1023) / 1024, 256>>>(w1, cw1, nff);
        cvt_half_k<<<(nff + 1023) / 1024, 256>>>(w2, cw2, nff);
        const int nlm = VOCAB * HID / 8;
        cvt_half_k<<<(nlm + 1023) / 1024, 256>>>(lm_w, wlm, nlm);
    }

    {
        int n = T_TOK * HID;
        embed_kernel<<<(n + 255) / 256, 256>>>(input_ids, tok_emb, pos_emb, x);
    }

    dim3 gqkv(HID / 128, T_TOK / 128, 3);   // 288
    dim3 gproj(HID / 64, T_TOK / 64);       // 384
    dim3 gff1(FFI / 128, T_TOK / 64);       // 24 x 32 = 768 (BM=64, BN=128)
    dim3 gff2(HID / 64, T_TOK / 64);        // 384
    dim3 gattn(SEQ / 64, NHEAD, BATCH);
    dim3 glm((VOCAB + 127) / 128, T_TOK / 128);

    for (int l = 0; l < NLAYER; l++) {
        const float* l1w = ln1_w + (size_t)l * HID;
        const float* l1b = ln1_b + (size_t)l * HID;
        const __half* qwl = wq + (size_t)l * HID * HID;
        const __half* kwl = wk + (size_t)l * HID * HID;
        const __half* vwl = wv + (size_t)l * HID * HID;
        const __half* owl = wo + (size_t)l * HID * HID;
        const float* obl = ob + (size_t)l * HID;
        const float* l2w = ln2_w + (size_t)l * HID;
        const float* l2b = ln2_b + (size_t)l * HID;
        const __half* w1l = cw1 + (size_t)l * FFI * HID;
        const float* b1l = b1 + (size_t)l * FFI;
        const __half* w2l = cw2 + (size_t)l * HID * FFI;
        const float* b2l = b2 + (size_t)l * HID;

        layernorm_kernel<<<T_TOK / 8, 256>>>(x, l1w, l1b, h);
        gemm_f16_qkv_k<<<gqkv, 256, GEMM_SMEM_128>>>(h, qwl, kwl, vwl, q, k, v, T_TOK, HID, HID);
        flash_attn_f16_kernel<<<gattn, 128>>>(q, k, v, attn_mask, a);
        gemm_f16_k<64, 64, false, false><<<gproj, 256, GEMM_SMEM_64>>>(a, owl, obl, x, (void*)x, T_TOK, HID, HID);

        layernorm_kernel<<<T_TOK / 8, 256>>>(x, l2w, l2b, h);
        gemm_f16_k<64, 128, true, true><<<gff1, 256, GEMM_SMEM_64128>>>(h, w1l, b1l, nullptr, (void*)ff, T_TOK, FFI, HID);
        gemm_f16_k<64, 64, false, false><<<gff2, 256, GEMM_SMEM_64>>>(ff, w2l, b2l, x, (void*)x, T_TOK, HID, FFI);
    }

    layernorm_kernel<<<T_TOK / 8, 256>>>(x, lnf_w, lnf_b, h);
    gemm_f16_k<128, 128, false, false><<<glm, 256, GEMM_SMEM_128>>>(h, wlm, nullptr, nullptr, (void*)out, T_TOK, VOCAB, HID);
}

// round 15
// speedup vs baseline: 1.0137x; 1.0137x over previous
#include <cuda_runtime.h>
#include <cuda_fp16.h>
#include <math.h>
#include <stdint.h>

#define T_TOK 2048
#define SEQ   1024
#define BATCH 2
#define HID   768
#define NHEAD 12
#define HDIM  64
#define NLAYER 12
#define FFI   3072
#define VOCAB 50257

// ---------------- scratch (device globals: allocation-free) ----------------
__device__ float  g_x[T_TOK * HID];
__device__ __half g_h[T_TOK * HID];
__device__ __half g_q[T_TOK * HID];
__device__ __half g_k[T_TOK * HID];
__device__ __half g_v[T_TOK * HID];
__device__ __half g_a[T_TOK * HID];
__device__ __half g_ff[T_TOK * FFI];
// fp16 weight copies
__device__ __half g_wq[NLAYER * HID * HID];
__device__ __half g_wk[NLAYER * HID * HID];
__device__ __half g_wv[NLAYER * HID * HID];
__device__ __half g_wo[NLAYER * HID * HID];
__device__ __half g_w1[NLAYER * FFI * HID];
__device__ __half g_w2[NLAYER * HID * FFI];
__device__ __half g_wlm[VOCAB * HID];

// ---------------- helpers ----------------
__device__ __forceinline__ float gelu1(float x) {
    return 0.5f * x * (1.0f + erff(x * 0.70710678118654752f));
}
__device__ __forceinline__ void mma_f16(float d[4], const uint32_t a[4], const uint32_t b[2]) {
    asm volatile(
        "mma.sync.aligned.m16n8k16.row.col.f32.f16.f16.f32 "
        "{%0,%1,%2,%3}, {%4,%5,%6,%7}, {%8,%9}, {%0,%1,%2,%3};\n"
        : "+f"(d[0]), "+f"(d[1]), "+f"(d[2]), "+f"(d[3])
        : "r"(a[0]), "r"(a[1]), "r"(a[2]), "r"(a[3]), "r"(b[0]), "r"(b[1]));
}
__device__ __forceinline__ void ldsm_x4(uint32_t* r, uint32_t addr) {
    asm volatile("ldmatrix.sync.aligned.m8n8.x4.shared.b16 {%0,%1,%2,%3}, [%4];"
        : "=r"(r[0]), "=r"(r[1]), "=r"(r[2]), "=r"(r[3]) : "r"(addr));
}
__device__ __forceinline__ void ldsm_x4_t(uint32_t* r, uint32_t addr) {
    asm volatile("ldmatrix.sync.aligned.m8n8.x4.trans.shared.b16 {%0,%1,%2,%3}, [%4];"
        : "=r"(r[0]), "=r"(r[1]), "=r"(r[2]), "=r"(r[3]) : "r"(addr));
}
__device__ __forceinline__ void cp_async16(uint32_t dst, const void* src, int sz) {
    asm volatile("cp.async.cg.shared.global [%0], [%1], 16, %2;\n"
                 :: "r"(dst), "l"(src), "r"(sz));
}
#define CP_COMMIT() asm volatile("cp.async.commit_group;\n" ::: "memory")

template<int N>
__device__ __forceinline__ void cp_wait() {
    asm volatile("cp.async.wait_group %0;\n" :: "n"(N) : "memory");
}

// ---------------- embeddings ----------------
__global__ void embed_kernel(const int* __restrict__ ids,
                             const float* __restrict__ tok,
                             const float* __restrict__ pos,
                             float* __restrict__ x) {
    int idx = blockIdx.x * blockDim.x + threadIdx.x;
    if (idx >= T_TOK * HID) return;
    int t = idx / HID;
    int hh = idx - t * HID;
    int s = t % SEQ;
    int id = ids[t];
    x[idx] = tok[(size_t)id * HID + hh] + pos[(size_t)s * HID + hh];
}

// ---------------- fp16 weight copy (8 floats -> uint4 store) --------------
__global__ void cvt_half_k(const float* __restrict__ in, __half* __restrict__ outp, int n8) {
    const int i0 = blockIdx.x * 1024 + threadIdx.x;
    #pragma unroll
    for (int c = 0; c < 4; c++) {
        const int i = i0 + c * 256;
        if (i < n8) {
            float4 a = reinterpret_cast<const float4*>(in)[2 * i];
            float4 b = reinterpret_cast<const float4*>(in)[2 * i + 1];
            __half2 h0 = __floats2half2_rn(a.x, a.y);
            __half2 h1 = __floats2half2_rn(a.z, a.w);
            __half2 h2 = __floats2half2_rn(b.x, b.y);
            __half2 h3 = __floats2half2_rn(b.z, b.w);
            uint4 u;
            u.x = *reinterpret_cast<uint32_t*>(&h0);
            u.y = *reinterpret_cast<uint32_t*>(&h1);
            u.z = *reinterpret_cast<uint32_t*>(&h2);
            u.w = *reinterpret_cast<uint32_t*>(&h3);
            reinterpret_cast<uint4*>(outp)[i] = u;
        }
    }
}

// ---------------- layernorm: one warp per row, register-resident ----------
__global__ __launch_bounds__(256) void layernorm_kernel(
    const float* __restrict__ x, const float* __restrict__ w,
    const float* __restrict__ b, __half* __restrict__ out)
{
    const int warp = threadIdx.x >> 5;
    const int lane = threadIdx.x & 31;
    const int row  = blockIdx.x * 8 + warp;
    const float* xr = x + (size_t)row * HID;
    __half* orow = out + (size_t)row * HID;

    float4 vv[6];
    #pragma unroll
    for (int i = 0; i < 6; i++)
        vv[i] = *reinterpret_cast<const float4*>(&xr[(i * 32 + lane) * 4]);

    float s = 0.f;
    #pragma unroll
    for (int i = 0; i < 6; i++) s += vv[i].x + vv[i].y + vv[i].z + vv[i].w;
    #pragma unroll
    for (int o = 16; o > 0; o >>= 1) s += __shfl_xor_sync(0xffffffffu, s, o);
    const float mean = s * (1.0f / (float)HID);

    float vs = 0.f;
    #pragma unroll
    for (int i = 0; i < 6; i++) {
        float d0 = vv[i].x - mean, d1 = vv[i].y - mean;
        float d2 = vv[i].z - mean, d3 = vv[i].w - mean;
        vs += d0 * d0 + d1 * d1 + d2 * d2 + d3 * d3;
    }
    #pragma unroll
    for (int o = 16; o > 0; o >>= 1) vs += __shfl_xor_sync(0xffffffffu, vs, o);
    const float inv = rsqrtf(vs * (1.0f / (float)HID) + 1e-5f);

    #pragma unroll
    for (int i = 0; i < 6; i++) {
        const int c = (i * 32 + lane) * 4;
        float4 wv = *reinterpret_cast<const float4*>(&w[c]);
        float4 bv = *reinterpret_cast<const float4*>(&b[c]);
        float y0 = (vv[i].x - mean) * inv * wv.x + bv.x;
        float y1 = (vv[i].y - mean) * inv * wv.y + bv.y;
        float y2 = (vv[i].z - mean) * inv * wv.z + bv.z;
        float y3 = (vv[i].w - mean) * inv * wv.w + bv.w;
        __half2 h0 = __floats2half2_rn(y0, y1);
        __half2 h1 = __floats2half2_rn(y2, y3);
        uint2 u;
        u.x = *reinterpret_cast<uint32_t*>(&h0);
        u.y = *reinterpret_cast<uint32_t*>(&h1);
        *reinterpret_cast<uint2*>(&orow[c]) = u;
    }
}

// ---------------- FP16 mma GEMM, ST-stage cp.async, ldmatrix --------------
#define HSTR 40

template<int BM, int BN, int ST, bool GELU, bool OUTHALF>
__device__ __forceinline__ void gemm_f16_dev(
    const __half* __restrict__ A, const __half* __restrict__ W,
    const float* __restrict__ bias, const float* __restrict__ res,
    void* __restrict__ Cv, int M, int N, int K)
{
    extern __shared__ __half smh[];
    constexpr int SH = (BM + BN) * HSTR;
    constexpr int MT = BM / 32;
    constexpr int NT = BN / 32;
    constexpr int WMROWS = BM / 2;
    constexpr int WNCOLS = BN / 4;

    const int tid  = threadIdx.x;
    const int warp = tid >> 5;
    const int lane = tid & 31;
    const int g    = lane >> 2;
    const int tig  = lane & 3;
    const int wm   = warp & 1;
    const int wn   = warp >> 1;

    const int m0 = blockIdx.y * BM;
    const int n0 = blockIdx.x * BN;

    const __half* gB;
    uint32_t dB;
    int bsz;
    if constexpr (BN == 128) {
        const int brl = tid >> 1;
        const int bk  = (tid & 1) << 4;
        const int bn  = n0 + brl;
        bsz = (bn < N) ? 16 : 0;
        gB = W + (size_t)(bn < N ? bn : 0) * K + bk;
        dB = (uint32_t)__cvta_generic_to_shared(smh + BM * HSTR + brl * HSTR + bk);
    } else {
        const int brl = tid >> 2;
        const int bk  = (tid & 3) << 3;
        const int bn  = n0 + brl;
        bsz = (bn < N) ? 16 : 0;
        gB = W + (size_t)(bn < N ? bn : 0) * K + bk;
        dB = (uint32_t)__cvta_generic_to_shared(smh + BM * HSTR + brl * HSTR + bk);
    }

    const __half* gA;
    uint32_t dA;
    if constexpr (BM == 128) {
        const int arl = tid >> 1;
        const int ak  = (tid & 1) << 4;
        gA = A + (size_t)(m0 + arl) * K + ak;
        dA = (uint32_t)__cvta_generic_to_shared(smh + arl * HSTR + ak);
    } else {
        const int arl = tid >> 2;
        const int ak  = (tid & 3) << 3;
        gA = A + (size_t)(m0 + arl) * K + ak;
        dA = (uint32_t)__cvta_generic_to_shared(smh + arl * HSTR + ak);
    }
    const uint32_t stageB = SH * 2u;

    const int alr = lane & 15;
    const int alc = (lane >> 4) * 8;
    const int bnr = (lane & 7) + ((lane >> 4) & 1) * 8;
    const int bkc = ((lane >> 3) & 1) * 8;

    float acc[MT][NT][4];
    #pragma unroll
    for (int i = 0; i < MT; i++)
        #pragma unroll
        for (int j = 0; j < NT; j++)
            #pragma unroll
            for (int r = 0; r < 4; r++) acc[i][j][r] = 0.f;

    const int NIT = K >> 5;

    #define FILLG2(it_) do { \
        const uint32_t _o = (uint32_t)((it_) % ST) * stageB; \
        const int _kb = (it_) << 5; \
        cp_async16(dA + _o, gA + _kb, 16); \
        if constexpr (BM == 128) cp_async16(dA + _o + 16, gA + _kb + 8, 16); \
        cp_async16(dB + _o, gB + _kb, bsz); \
        if constexpr (BN == 128) cp_async16(dB + _o + 16, gB + _kb + 8, bsz); \
    } while (0)

    #pragma unroll
    for (int s = 0; s < ST - 1; s++) {
        if (s < NIT) FILLG2(s);
        CP_COMMIT();
    }
    cp_wait<ST - 2>();
    __syncthreads();

    for (int it = 0; it < NIT; it++) {
        const int buf = it % ST;
        const __half* bufA = smh + buf * SH;
        const __half* bufB = bufA + BM * HSTR;

        #pragma unroll
        for (int s = 0; s < 2; s++) {
            uint32_t af[MT][4];
            #pragma unroll
            for (int mt = 0; mt < MT; mt++)
                ldsm_x4(af[mt], (uint32_t)__cvta_generic_to_shared(
                    &bufA[(wm * WMROWS + mt * 16 + alr) * HSTR + s * 16 + alc]));
            uint32_t bf[NT][2];
            #pragma unroll
            for (int p = 0; p < NT / 2; p++) {
                uint32_t bq[4];
                ldsm_x4(bq, (uint32_t)__cvta_generic_to_shared(
                    &bufB[(wn * WNCOLS + p * 16 + bnr) * HSTR + s * 16 + bkc]));
                bf[2 * p][0] = bq[0]; bf[2 * p][1] = bq[1];
                bf[2 * p + 1][0] = bq[2]; bf[2 * p + 1][1] = bq[3];
            }
            #pragma unroll
            for (int mt = 0; mt < MT; mt++)
                #pragma unroll
                for (int nt = 0; nt < NT; nt++)
                    mma_f16(acc[mt][nt], af[mt], bf[nt]);
        }

        const int nit = it + ST - 1;
        if (nit < NIT) FILLG2(nit);
        CP_COMMIT();
        cp_wait<ST - 2>();
        __syncthreads();
    }
    #undef FILLG2

    float* Cf = (float*)Cv;
    __half* Ch = (__half*)Cv;
    const bool n_even = ((N & 1) == 0);
    #pragma unroll
    for (int mt = 0; mt < MT; mt++) {
        const int r0 = m0 + wm * WMROWS + mt * 16 + g;
        #pragma unroll
        for (int nt = 0; nt < NT; nt++) {
            const int c = n0 + wn * WNCOLS + nt * 8 + tig * 2;
            #pragma unroll
            for (int half_ = 0; half_ < 2; half_++) {
                const int m = r0 + half_ * 8;
                float v0 = acc[mt][nt][half_ * 2 + 0];
                float v1 = acc[mt][nt][half_ * 2 + 1];
                if (n_even && (c + 1) < N) {
                    if (bias) { float2 bv = *reinterpret_cast<const float2*>(&bias[c]); v0 += bv.x; v1 += bv.y; }
                    if (res)  { float2 rv = *reinterpret_cast<const float2*>(&res[(size_t)m * N + c]); v0 += rv.x; v1 += rv.y; }
                    if (GELU) { v0 = gelu1(v0); v1 = gelu1(v1); }
                    if (OUTHALF) {
                        *reinterpret_cast<__half2*>(&Ch[(size_t)m * N + c]) = __floats2half2_rn(v0, v1);
                    } else {
                        *reinterpret_cast<float2*>(&Cf[(size_t)m * N + c]) = make_float2(v0, v1);
                    }
                } else {
                    #pragma unroll
                    for (int q2 = 0; q2 < 2; q2++) {
                        const int n = c + q2;
                        if (n < N) {
                            float val = (q2 == 0) ? v0 : v1;
                            if (bias) val += bias[n];
                            if (res)  val += res[(size_t)m * N + n];
                            if (GELU) val = gelu1(val);
                            if (OUTHALF) Ch[(size_t)m * N + n] = __float2half_rn(val);
                            else         Cf[(size_t)m * N + n] = val;
                        }
                    }
                }
            }
        }
    }
}

template<int BM, int BN, int ST, int MINB, bool GELU, bool OUTHALF>
__global__ __launch_bounds__(256, MINB) void gemm_f16_k(
    const __half* __restrict__ A, const __half* __restrict__ W,
    const float* __restrict__ bias, const float* __restrict__ res,
    void* __restrict__ C, int M, int N, int K)
{
    gemm_f16_dev<BM, BN, ST, GELU, OUTHALF>(A, W, bias, res, C, M, N, K);
}

__global__ __launch_bounds__(256, 2) void gemm_f16_qkv_k(
    const __half* __restrict__ A,
    const __half* __restrict__ w0, const __half* __restrict__ w1, const __half* __restrict__ w2,
    __half* __restrict__ o0, __half* __restrict__ o1, __half* __restrict__ o2,
    int M, int N, int K)
{
    const __half* W = (blockIdx.z == 0) ? w0 : ((blockIdx.z == 1) ? w1 : w2);
    __half* C = (blockIdx.z == 0) ? o0 : ((blockIdx.z == 1) ? o1 : o2);
    gemm_f16_dev<128, 128, 4, false, true>(A, W, nullptr, nullptr, (void*)C, M, N, K);
}

#define GEMM_SMEM_128 (4 * (128 + 128) * HSTR * 2)
#define GEMM_SMEM_64  (3 * (64 + 64) * HSTR * 2)

// ---------------- tensor-core flash attention (R13 single-buffer) ---------
#define ASTR 72

__global__ __launch_bounds__(128) void flash_attn_f16_kernel(
    const __half* __restrict__ q, const __half* __restrict__ k,
    const __half* __restrict__ v, const int* __restrict__ amask,
    __half* __restrict__ out)
{
    __shared__ __half Qs[64 * ASTR];
    __shared__ __half Ks[64 * ASTR];
    __shared__ __half Vs[64 * ASTR];
    __shared__ int msk[64];

    const int qt = gridDim.x - 1 - blockIdx.x;
    const int hh = blockIdx.y;
    const int b  = blockIdx.z;
    const int q0 = qt * 64;
    const int tid = threadIdx.x;
    const int lane = tid & 31;
    const int w = tid >> 5;
    const int tig = lane & 3;
    const int gid = lane >> 2;

    {
        const __half2 s125 = __float2half2_rn(0.125f);
        #pragma unroll
        for (int ch = tid; ch < 512; ch += 128) {
            const int row = ch >> 3, part = ch & 7;
            uint4 u = *reinterpret_cast<const uint4*>(
                q + (size_t)(b * SEQ + q0 + row) * HID + hh * HDIM + part * 8);
            __half2* hp = reinterpret_cast<__half2*>(&u);
            hp[0] = __hmul2(hp[0], s125); hp[1] = __hmul2(hp[1], s125);
            hp[2] = __hmul2(hp[2], s125); hp[3] = __hmul2(hp[3], s125);
            *reinterpret_cast<uint4*>(&Qs[row * ASTR + part * 8]) = u;
        }
    }
    __syncthreads();

    uint32_t qf[4][4];
    {
        const int r = 16 * w + (lane & 15);
        const int c = (lane >> 4) * 8;
        #pragma unroll
        for (int kk = 0; kk < 4; kk++)
            ldsm_x4(qf[kk], (uint32_t)__cvta_generic_to_shared(&Qs[r * ASTR + kk * 16 + c]));
    }

    float o[8][4];
    #pragma unroll
    for (int i = 0; i < 8; i++)
        #pragma unroll
        for (int j = 0; j < 4; j++) o[i][j] = 0.f;
    float mi0 = -1e30f, mi1 = -1e30f, li0 = 0.f, li1 = 0.f;
    const int row0 = q0 + 16 * w + gid;
    const int row1 = row0 + 8;

    for (int kt = 0; kt <= qt; kt++) {
        __syncthreads();
        #pragma unroll
        for (int ch = tid; ch < 512; ch += 128) {
            const int row = ch >> 3, part = ch & 7;
            const size_t go = (size_t)(b * SEQ + kt * 64 + row) * HID + hh * HDIM + part * 8;
            *reinterpret_cast<uint4*>(&Ks[row * ASTR + part * 8]) =
                *reinterpret_cast<const uint4*>(k + go);
            *reinterpret_cast<uint4*>(&Vs[row * ASTR + part * 8]) =
                *reinterpret_cast<const uint4*>(v + go);
        }
        if (tid < 64) msk[tid] = amask[b * SEQ + kt * 64 + tid];
        __syncthreads();

        float s[8][4];
        #pragma unroll
        for (int j = 0; j < 8; j++) {
            s[j][0] = s[j][1] = s[j][2] = s[j][3] = 0.f;
            uint32_t kb[8];
            const uint32_t base = (uint32_t)__cvta_generic_to_shared(
                &Ks[(8 * j + (lane & 7)) * ASTR + (lane >> 3) * 8]);
            ldsm_x4(kb, base);
            ldsm_x4(kb + 4, base + 64);
            mma_f16(s[j], qf[0], kb);
            mma_f16(s[j], qf[1], kb + 2);
            mma_f16(s[j], qf[2], kb + 4);
            mma_f16(s[j], qf[3], kb + 6);
        }

        const bool diag = (kt == qt);
        #pragma unroll
        for (int j = 0; j < 8; j++) {
            const int c0i = kt * 64 + 8 * j + 2 * tig;
            if (msk[8 * j + 2 * tig] == 0)     { s[j][0] = -1e9f; s[j][2] = -1e9f; }
            if (msk[8 * j + 2 * tig + 1] == 0) { s[j][1] = -1e9f; s[j][3] = -1e9f; }
            if (diag) {
                if (c0i > row0)     s[j][0] = -1e9f;
                if (c0i + 1 > row0) s[j][1] = -1e9f;
                if (c0i > row1)     s[j][2] = -1e9f;
                if (c0i + 1 > row1) s[j][3] = -1e9f;
            }
        }

        float m0 = -1e30f, m1 = -1e30f;
        #pragma unroll
        for (int j = 0; j < 8; j++) {
            m0 = fmaxf(m0, fmaxf(s[j][0], s[j][1]));
            m1 = fmaxf(m1, fmaxf(s[j][2], s[j][3]));
        }
        m0 = fmaxf(m0, __shfl_xor_sync(0xffffffffu, m0, 1));
        m0 = fmaxf(m0, __shfl_xor_sync(0xffffffffu, m0, 2));
        m1 = fmaxf(m1, __shfl_xor_sync(0xffffffffu, m1, 1));
        m1 = fmaxf(m1, __shfl_xor_sync(0xffffffffu, m1, 2));
        const float mn0 = fmaxf(mi0, m0);
        const float mn1 = fmaxf(mi1, m1);
        const float sc0 = __expf(mi0 - mn0);
        const float sc1 = __expf(mi1 - mn1);

        uint32_t ph[8][2];
        float ls0 = 0.f, ls1 = 0.f;
        #pragma unroll
        for (int j = 0; j < 8; j++) {
            const float p0 = __expf(s[j][0] - mn0);
            const float p1 = __expf(s[j][1] - mn0);
            const float p2 = __expf(s[j][2] - mn1);
            const float p3 = __expf(s[j][3] - mn1);
            ls0 += p0 + p1; ls1 += p2 + p3;
            __half2 h01 = __floats2half2_rn(p0, p1);
            __half2 h23 = __floats2half2_rn(p2, p3);
            ph[j][0] = *reinterpret_cast<uint32_t*>(&h01);
            ph[j][1] = *reinterpret_cast<uint32_t*>(&h23);
        }
        li0 = li0 * sc0 + ls0;
        li1 = li1 * sc1 + ls1;
        mi0 = mn0; mi1 = mn1;
        #pragma unroll
        for (int dn = 0; dn < 8; dn++) {
            o[dn][0] *= sc0; o[dn][1] *= sc0;
            o[dn][2] *= sc1; o[dn][3] *= sc1;
        }

        #pragma unroll
        for (int kj = 0; kj < 4; kj++) {
            const uint32_t a[4] = {ph[2 * kj][0], ph[2 * kj][1],
                                   ph[2 * kj + 1][0], ph[2 * kj + 1][1]};
            #pragma unroll
            for (int dnp = 0; dnp < 4; dnp++) {
                uint32_t vb[4];
                const uint32_t addr = (uint32_t)__cvta_generic_to_shared(
                    &Vs[(16 * kj + (lane & 7) + ((lane >> 3) & 1) * 8) * ASTR
                        + 16 * dnp + (lane >> 4) * 8]);
                ldsm_x4_t(vb, addr);
                mma_f16(o[2 * dnp], a, vb);
                mma_f16(o[2 * dnp + 1], a, vb + 2);
            }
        }
    }

    li0 += __shfl_xor_sync(0xffffffffu, li0, 1);
    li0 += __shfl_xor_sync(0xffffffffu, li0, 2);
    li1 += __shfl_xor_sync(0xffffffffu, li1, 1);
    li1 += __shfl_xor_sync(0xffffffffu, li1, 2);
    const float inv0 = 1.0f / li0;
    const float inv1 = 1.0f / li1;
    #pragma unroll
    for (int dn = 0; dn < 8; dn++) {
        const int cb = hh * HDIM + 8 * dn + 2 * tig;
        __half2 h0 = __floats2half2_rn(o[dn][0] * inv0, o[dn][1] * inv0);
        __half2 h1 = __floats2half2_rn(o[dn][2] * inv1, o[dn][3] * inv1);
        *reinterpret_cast<__half2*>(&out[(size_t)(b * SEQ + row0) * HID + cb]) = h0;
        *reinterpret_cast<__half2*>(&out[(size_t)(b * SEQ + row1) * HID + cb]) = h1;
    }
}

// ---------------- launcher ----------------
extern "C" void kernel_launch(void* const* d_in, const int* in_sizes, int n_in,
                              void* d_out, int out_size) {
    const int*   input_ids = (const int*)d_in[0];
    const int*   attn_mask = (const int*)d_in[1];
    const float* tok_emb   = (const float*)d_in[2];
    const float* pos_emb   = (const float*)d_in[3];
    const float* ln1_w     = (const float*)d_in[4];
    const float* ln1_b     = (const float*)d_in[5];
    const float* qw        = (const float*)d_in[6];
    const float* kw        = (const float*)d_in[7];
    const float* vw        = (const float*)d_in[8];
    const float* ow        = (const float*)d_in[9];
    const float* ob        = (const float*)d_in[10];
    const float* ln2_w     = (const float*)d_in[11];
    const float* ln2_b     = (const float*)d_in[12];
    const float* w1        = (const float*)d_in[13];
    const float* b1        = (const float*)d_in[14];
    const float* w2        = (const float*)d_in[15];
    const float* b2        = (const float*)d_in[16];
    const float* lnf_w     = (const float*)d_in[17];
    const float* lnf_b     = (const float*)d_in[18];
    const float* lm_w      = (const float*)d_in[19];
    float* out = (float*)d_out;

    float *x;
    __half *h, *q, *k, *v, *a, *ff, *wq, *wk, *wv, *wo, *cw1, *cw2, *wlm;
    cudaGetSymbolAddress((void**)&x,  g_x);
    cudaGetSymbolAddress((void**)&h,  g_h);
    cudaGetSymbolAddress((void**)&q,  g_q);
    cudaGetSymbolAddress((void**)&k,  g_k);
    cudaGetSymbolAddress((void**)&v,  g_v);
    cudaGetSymbolAddress((void**)&a,  g_a);
    cudaGetSymbolAddress((void**)&ff, g_ff);
    cudaGetSymbolAddress((void**)&wq, g_wq);
    cudaGetSymbolAddress((void**)&wk, g_wk);
    cudaGetSymbolAddress((void**)&wv, g_wv);
    cudaGetSymbolAddress((void**)&wo, g_wo);
    cudaGetSymbolAddress((void**)&cw1, g_w1);
    cudaGetSymbolAddress((void**)&cw2, g_w2);
    cudaGetSymbolAddress((void**)&wlm, g_wlm);

    cudaFuncSetAttribute((const void*)gemm_f16_k<128, 128, 4, 2, false, false>,
                         cudaFuncAttributeMaxDynamicSharedMemorySize, GEMM_SMEM_128);
    cudaFuncSetAttribute((const void*)gemm_f16_k<128, 128, 4, 2, true, true>,
                         cudaFuncAttributeMaxDynamicSharedMemorySize, GEMM_SMEM_128);
    cudaFuncSetAttribute((const void*)gemm_f16_k<64, 64, 3, 3, false, false>,
                         cudaFuncAttributeMaxDynamicSharedMemorySize, GEMM_SMEM_64);
    cudaFuncSetAttribute((const void*)gemm_f16_qkv_k,
                         cudaFuncAttributeMaxDynamicSharedMemorySize, GEMM_SMEM_128);

    // one-time-per-launch fp16 weight conversion
    {
        const int nqk = NLAYER * HID * HID / 8;
        cvt_half_k<<<(nqk + 1023) / 1024, 256>>>(qw, wq, nqk);
        cvt_half_k<<<(nqk + 1023) / 1024, 256>>>(kw, wk, nqk);
        cvt_half_k<<<(nqk + 1023) / 1024, 256>>>(vw, wv, nqk);
        cvt_half_k<<<(nqk + 1023) / 1024, 256>>>(ow, wo, nqk);
        const int nff = NLAYER * FFI * HID / 8;
        cvt_half_k<<<(nff + 1023) / 1024, 256>>>(w1, cw1, nff);
        cvt_half_k<<<(nff + 1023) / 1024, 256>>>(w2, cw2, nff);
        const int nlm = VOCAB * HID / 8;
        cvt_half_k<<<(nlm + 1023) / 1024, 256>>>(lm_w, wlm, nlm);
    }

    {
        int n = T_TOK * HID;
        embed_kernel<<<(n + 255) / 256, 256>>>(input_ids, tok_emb, pos_emb, x);
    }

    dim3 gqkv(HID / 128, T_TOK / 128, 3);   // 288
    dim3 gproj(HID / 64, T_TOK / 64);       // 384
    dim3 gff1(FFI / 128, T_TOK / 128);      // 384
    dim3 gff2(HID / 64, T_TOK / 64);        // 384
    dim3 gattn(SEQ / 64, NHEAD, BATCH);
    dim3 glm((VOCAB + 127) / 128, T_TOK / 128);

    for (int l = 0; l < NLAYER; l++) {
        const float* l1w = ln1_w + (size_t)l * HID;
        const float* l1b = ln1_b + (size_t)l * HID;
        const __half* qwl = wq + (size_t)l * HID * HID;
        const __half* kwl = wk + (size_t)l * HID * HID;
        const __half* vwl = wv + (size_t)l * HID * HID;
        const __half* owl = wo + (size_t)l * HID * HID;
        const float* obl = ob + (size_t)l * HID;
        const float* l2w = ln2_w + (size_t)l * HID;
        const float* l2b = ln2_b + (size_t)l * HID;
        const __half* w1l = cw1 + (size_t)l * FFI * HID;
        const float* b1l = b1 + (size_t)l * FFI;
        const __half* w2l = cw2 + (size_t)l * HID * FFI;
        const float* b2l = b2 + (size_t)l * HID;

        layernorm_kernel<<<T_TOK / 8, 256>>>(x, l1w, l1b, h);
        gemm_f16_qkv_k<<<gqkv, 256, GEMM_SMEM_128>>>(h, qwl, kwl, vwl, q, k, v, T_TOK, HID, HID);
        flash_attn_f16_kernel<<<gattn, 128>>>(q, k, v, attn_mask, a);
        gemm_f16_k<64, 64, 3, 3, false, false><<<gproj, 256, GEMM_SMEM_64>>>(a, owl, obl, x, (void*)x, T_TOK, HID, HID);

        layernorm_kernel<<<T_TOK / 8, 256>>>(x, l2w, l2b, h);
        gemm_f16_k<128, 128, 4, 2, true, true><<<gff1, 256, GEMM_SMEM_128>>>(h, w1l, b1l, nullptr, (void*)ff, T_TOK, FFI, HID);
        gemm_f16_k<64, 64, 3, 3, false, false><<<gff2, 256, GEMM_SMEM_64>>>(ff, w2l, b2l, x, (void*)x, T_TOK, HID, FFI);
    }

    layernorm_kernel<<<T_TOK / 8, 256>>>(x, lnf_w, lnf_b, h);
    gemm_f16_k<128, 128, 4, 2, false, false><<<glm, 256, GEMM_SMEM_128>>>(h, wlm, nullptr, nullptr, (void*)out, T_TOK, VOCAB, HID);
}